// round 6
// baseline (speedup 1.0000x reference)
#include <cuda_runtime.h>
#include <cuda_bf16.h>
#include <cuda_fp16.h>
#include <cstdint>

#define BB 2
#define SS 2048
#define DD 1024
#define HH 16
#define MM (BB*SS)             // 4096

// GEMM tiling: 64x128 tile, K-chunk 32 (64B rows, SW64-style swizzle)
#define TM 64
#define TN 128
#define KC 32
#define NCH (DD/KC)            // 32
#define NSTAGE 3
#define OFF_AHI 0
#define OFF_ALO 4096
#define OFF_BHI 8192
#define OFF_BLO 16384
#define STAGE_BYTES 24576
#define GEMM_SMEM (NSTAGE*STAGE_BYTES)   // 73728

#define QKV_TILES 1536         // 3 * (MM/TM=64) * (DD/TN=8)
#define OUT_TILES 512          // 64 * 8

// lo-term scaling (keeps fp16 correction products in normal range)
#define SCL  2048.0f
#define INVS 4.8828125e-4f     // 1/2048

// Attention tiling
#define BQ 64
#define AROWS 128
#define AST 66
#define ATT_SMEM ((AROWS*AST*2 + BQ*AST + 8*68)*4)   // 86656 B

// ---------------------------------------------------------------------------
// Scratch (device globals: allocation-free rule)
// ---------------------------------------------------------------------------
__device__ float g_Q[(size_t)MM * DD];
__device__ float g_K[(size_t)MM * DD];
__device__ float g_V[(size_t)MM * DD];
__device__ __half g_Ahi[(size_t)MM * DD];
__device__ __half g_Alo[(size_t)MM * DD];
__device__ __half g_Whi[(size_t)4 * DD * DD];   // wq,wk,wv,wo
__device__ __half g_Wlo[(size_t)4 * DD * DD];
__device__ __half g_Chi[(size_t)MM * DD];
__device__ __half g_Clo[(size_t)MM * DD];

// ---------------------------------------------------------------------------
// Helpers
// ---------------------------------------------------------------------------
__device__ __forceinline__ uint32_t smem_u32(const void* p) {
    uint32_t a;
    asm("{ .reg .u64 t; cvta.to.shared.u64 t, %1; cvt.u32.u64 %0, t; }"
        : "=r"(a) : "l"(p));
    return a;
}

__device__ __forceinline__ void cpasync16(uint32_t dst, const void* src) {
    asm volatile("cp.async.cg.shared.global [%0], [%1], 16;"
                 :: "r"(dst), "l"(src));
}
#define CP_COMMIT() asm volatile("cp.async.commit_group;" ::: "memory")
#define CP_WAIT1()  asm volatile("cp.async.wait_group 1;" ::: "memory")
#define CP_WAIT0()  asm volatile("cp.async.wait_group 0;" ::: "memory")

__device__ __forceinline__ void ldm4(uint32_t* r, uint32_t addr) {
    asm volatile("ldmatrix.sync.aligned.m8n8.x4.shared.b16 {%0,%1,%2,%3}, [%4];"
                 : "=r"(r[0]), "=r"(r[1]), "=r"(r[2]), "=r"(r[3]) : "r"(addr));
}

__device__ __forceinline__ void mma_f32(float* c, const uint32_t* a,
                                        uint32_t b0, uint32_t b1) {
    asm volatile(
        "mma.sync.aligned.m16n8k16.row.col.f32.f16.f16.f32 "
        "{%0,%1,%2,%3}, {%4,%5,%6,%7}, {%8,%9}, {%0,%1,%2,%3};"
        : "+f"(c[0]), "+f"(c[1]), "+f"(c[2]), "+f"(c[3])
        : "r"(a[0]), "r"(a[1]), "r"(a[2]), "r"(a[3]), "r"(b0), "r"(b1));
}

__device__ __forceinline__ void mma_f16(uint32_t* c, const uint32_t* a,
                                        uint32_t b0, uint32_t b1) {
    asm volatile(
        "mma.sync.aligned.m16n8k16.row.col.f16.f16.f16.f16 "
        "{%0,%1}, {%2,%3,%4,%5}, {%6,%7}, {%0,%1};"
        : "+r"(c[0]), "+r"(c[1])
        : "r"(a[0]), "r"(a[1]), "r"(a[2]), "r"(a[3]), "r"(b0), "r"(b1));
}

__device__ __forceinline__ void hsplit(float x, __half& h, __half& l) {
    h = __float2half_rn(x);
    l = __float2half_rn((x - __half2float(h)) * SCL);
}

// ---------------------------------------------------------------------------
// Split pass: q + 4 weights -> fp16 hi / scaled-lo
// ---------------------------------------------------------------------------
__global__ void __launch_bounds__(256) split_kernel(const float* __restrict__ q,
                                                    const float* __restrict__ wq,
                                                    const float* __restrict__ wk,
                                                    const float* __restrict__ wv,
                                                    const float* __restrict__ wo)
{
    const size_t i4 = (size_t)blockIdx.x * 256 + threadIdx.x;
    const float* src;
    __half *dhi, *dlo;
    size_t e;
    if (i4 < 1048576) {
        src = q; e = i4;
        dhi = g_Ahi; dlo = g_Alo;
    } else {
        const size_t r = i4 - 1048576;
        const int w = (int)(r >> 18);
        e = r & 262143;
        src = (w == 0) ? wq : (w == 1) ? wk : (w == 2) ? wv : wo;
        dhi = g_Whi + (size_t)w * DD * DD;
        dlo = g_Wlo + (size_t)w * DD * DD;
    }
    const float4 v = ((const float4*)src)[e];
    __half h[4], l[4];
    hsplit(v.x, h[0], l[0]); hsplit(v.y, h[1], l[1]);
    hsplit(v.z, h[2], l[2]); hsplit(v.w, h[3], l[3]);
    *(ushort4*)(dhi + e * 4) = make_ushort4(*(unsigned short*)&h[0], *(unsigned short*)&h[1],
                                            *(unsigned short*)&h[2], *(unsigned short*)&h[3]);
    *(ushort4*)(dlo + e * 4) = make_ushort4(*(unsigned short*)&l[0], *(unsigned short*)&l[1],
                                            *(unsigned short*)&l[2], *(unsigned short*)&l[3]);
}

// ---------------------------------------------------------------------------
// Persistent fp16 GEMM tile engine: C[64x128 tile] = A @ W^T (+bias)
// 8 warps as 2(M) x 4(N); warp subtile 32x32.
// ---------------------------------------------------------------------------
struct TileCtx {
    uint32_t sb;
    uint32_t aoff[2][2];   // [kk][mi]
    uint32_t boff[2][2];   // [kk][nb]
    int wm, wn, lane;
};

__device__ __forceinline__ void tile_init(TileCtx& T, uint32_t sb) {
    const int tid = threadIdx.x;
    const int wid = tid >> 5;
    T.lane = tid & 31;
    T.wm = wid >> 2;
    T.wn = wid & 3;
    T.sb = sb;
#pragma unroll
    for (int kk = 0; kk < 2; ++kk) {
        const int c16 = kk * 2 + (T.lane >> 4);
#pragma unroll
        for (int mi = 0; mi < 2; ++mi) {
            const int row = T.wm * 32 + mi * 16 + (T.lane & 15);
            T.aoff[kk][mi] = row * 64 + ((c16 ^ ((row >> 1) & 3)) << 4);
        }
#pragma unroll
        for (int nb = 0; nb < 2; ++nb) {
            const int row = T.wn * 32 + nb * 16 + (T.lane & 15);
            T.boff[kk][nb] = row * 64 + ((c16 ^ ((row >> 1) & 3)) << 4);
        }
    }
}

__device__ __forceinline__ void tile_issue(const TileCtx& T,
                                           const __half* Ahi_t, const __half* Alo_t,
                                           const __half* Bhi_t, const __half* Blo_t,
                                           int kc, int stg)
{
    const int tid = threadIdx.x;
    const uint32_t base = T.sb + stg * STAGE_BYTES;
    {   // A: 64 rows x 64B per array = 256 slots
        const int r = tid >> 2, c = tid & 3;
        const uint32_t sw = r * 64 + ((c ^ ((r >> 1) & 3)) << 4);
        const size_t go = (size_t)r * DD + kc * KC + c * 8;
        cpasync16(base + OFF_AHI + sw, Ahi_t + go);
        cpasync16(base + OFF_ALO + sw, Alo_t + go);
    }
#pragma unroll
    for (int it = 0; it < 2; ++it) {  // B: 128 rows = 512 slots
        const int id = tid + it * 256;
        const int r = id >> 2, c = id & 3;
        const uint32_t sw = r * 64 + ((c ^ ((r >> 1) & 3)) << 4);
        const size_t go = (size_t)r * DD + kc * KC + c * 8;
        cpasync16(base + OFF_BHI + sw, Bhi_t + go);
        cpasync16(base + OFF_BLO + sw, Blo_t + go);
    }
    CP_COMMIT();
}

__device__ __forceinline__ void tile_compute(const TileCtx& T,
                                             const __half* Ahi_t, const __half* Alo_t,
                                             const __half* Bhi_t, const __half* Blo_t,
                                             float* __restrict__ C, size_t ldc,
                                             int brow, int bcol,
                                             const float* __restrict__ bias)
{
    float acc[2][4][4];
    uint32_t hacc[2][4][2];
#pragma unroll
    for (int a = 0; a < 2; ++a)
#pragma unroll
        for (int b = 0; b < 4; ++b) {
#pragma unroll
            for (int c = 0; c < 4; ++c) acc[a][b][c] = 0.f;
            hacc[a][b][0] = 0u; hacc[a][b][1] = 0u;
        }

    __syncthreads();   // smem reuse guard across persistent tiles
    tile_issue(T, Ahi_t, Alo_t, Bhi_t, Blo_t, 0, 0);
    tile_issue(T, Ahi_t, Alo_t, Bhi_t, Blo_t, 1, 1);

    for (int kc = 0; kc < NCH; ++kc) {
        if (kc + 1 < NCH) CP_WAIT1(); else CP_WAIT0();
        __syncthreads();
        if (kc + 2 < NCH)
            tile_issue(T, Ahi_t, Alo_t, Bhi_t, Blo_t, kc + 2, (kc + 2) % NSTAGE);

        const uint32_t st = T.sb + (kc % NSTAGE) * STAGE_BYTES;
#pragma unroll
        for (int kk = 0; kk < 2; ++kk) {
            uint32_t ah[2][4], bh[2][4];
#pragma unroll
            for (int mi = 0; mi < 2; ++mi) ldm4(ah[mi], st + OFF_AHI + T.aoff[kk][mi]);
#pragma unroll
            for (int nb = 0; nb < 2; ++nb) ldm4(bh[nb], st + OFF_BHI + T.boff[kk][nb]);
#pragma unroll
            for (int mi = 0; mi < 2; ++mi)
#pragma unroll
                for (int ni = 0; ni < 4; ++ni) {
                    const int nb = ni >> 1, s = ni & 1;
                    mma_f32(acc[mi][ni], ah[mi], bh[nb][s], bh[nb][s + 2]);
                }
            uint32_t al[2][4], bl[2][4];
#pragma unroll
            for (int mi = 0; mi < 2; ++mi) ldm4(al[mi], st + OFF_ALO + T.aoff[kk][mi]);
#pragma unroll
            for (int nb = 0; nb < 2; ++nb) ldm4(bl[nb], st + OFF_BLO + T.boff[kk][nb]);
#pragma unroll
            for (int mi = 0; mi < 2; ++mi)
#pragma unroll
                for (int ni = 0; ni < 4; ++ni) {
                    const int nb = ni >> 1, s = ni & 1;
                    mma_f16(hacc[mi][ni], al[mi], bh[nb][s], bh[nb][s + 2]);
                    mma_f16(hacc[mi][ni], ah[mi], bl[nb][s], bl[nb][s + 2]);
                }
        }
    }

#pragma unroll
    for (int mi = 0; mi < 2; ++mi) {
        const int row = brow + T.wm * 32 + mi * 16 + (T.lane >> 2);
#pragma unroll
        for (int ni = 0; ni < 4; ++ni) {
            const int col = bcol + T.wn * 32 + ni * 8 + (T.lane & 3) * 2;
            const float2 c01 = __half22float2(*(const __half2*)&hacc[mi][ni][0]);
            const float2 c23 = __half22float2(*(const __half2*)&hacc[mi][ni][1]);
            float2 v0 = make_float2(fmaf(c01.x, INVS, acc[mi][ni][0]),
                                    fmaf(c01.y, INVS, acc[mi][ni][1]));
            float2 v1 = make_float2(fmaf(c23.x, INVS, acc[mi][ni][2]),
                                    fmaf(c23.y, INVS, acc[mi][ni][3]));
            if (bias) {
                const float b0 = bias[col], b1 = bias[col + 1];
                v0.x += b0; v0.y += b1; v1.x += b0; v1.y += b1;
            }
            *(float2*)&C[(size_t)row * ldc + col]       = v0;
            *(float2*)&C[(size_t)(row + 8) * ldc + col] = v1;
        }
    }
}

__global__ void __launch_bounds__(256, 1) qkv_p()
{
    extern __shared__ char dsm[];
    TileCtx T;
    tile_init(T, smem_u32(dsm));
    for (int t = blockIdx.x; t < QKV_TILES; t += gridDim.x) {
        const int z = t >> 9;              // 512 tiles per z
        const int rem = t & 511;
        const int brow = (rem >> 3) << 6;  // TM=64
        const int bcol = (rem & 7) << 7;   // TN=128
        float* Cc = (z == 0) ? g_Q : ((z == 1) ? g_K : g_V);
        const __half* Whi = g_Whi + (size_t)z * DD * DD;
        const __half* Wlo = g_Wlo + (size_t)z * DD * DD;
        tile_compute(T,
                     g_Ahi + (size_t)brow * DD, g_Alo + (size_t)brow * DD,
                     Whi + (size_t)bcol * DD,   Wlo + (size_t)bcol * DD,
                     Cc, DD, brow, bcol, nullptr);
    }
}

__global__ void __launch_bounds__(256, 1) out_p(const float* __restrict__ bo,
                                                float* __restrict__ out)
{
    extern __shared__ char dsm[];
    TileCtx T;
    tile_init(T, smem_u32(dsm));
    const __half* Whi = g_Whi + (size_t)3 * DD * DD;
    const __half* Wlo = g_Wlo + (size_t)3 * DD * DD;
    for (int t = blockIdx.x; t < OUT_TILES; t += gridDim.x) {
        const int brow = (t >> 3) << 6;
        const int bcol = (t & 7) << 7;
        tile_compute(T,
                     g_Chi + (size_t)brow * DD, g_Clo + (size_t)brow * DD,
                     Whi + (size_t)bcol * DD,   Wlo + (size_t)bcol * DD,
                     out, DD, brow, bcol, bo);
    }
}

// ---------------------------------------------------------------------------
// Local-window attention, lane-per-key. Block = 64 queries x (b,h).
// ---------------------------------------------------------------------------
__global__ void __launch_bounds__(256) attn_blk(float* __restrict__ attn_out)
{
    extern __shared__ float s[];
    float* Ks = s;
    float* Vs = Ks + AROWS * AST;
    float* Qs = Vs + AROWS * AST;
    float* ps = Qs + BQ * AST;

    const int tid  = threadIdx.x;
    const int warp = tid >> 5;
    const int lane = tid & 31;
    const int q0   = blockIdx.x * BQ;
    const int bh   = blockIdx.y;
    const int h    = bh & (HH - 1);
    const int b    = bh >> 4;
    const int jbase = q0 - 32;

    const float* Kg = g_K + (size_t)b * SS * DD + h * 64;
    const float* Vg = g_V + (size_t)b * SS * DD + h * 64;
    const float* Qg = g_Q + ((size_t)(b * SS + q0)) * DD + h * 64;

    for (int idx = tid; idx < AROWS * 16; idx += 256) {
        const int r = idx >> 4, c4 = (idx & 15) * 4;
        const int j = jbase + r;
        if (j >= 0 && j < SS) {
            const float4 kv = *(const float4*)&Kg[(size_t)j * DD + c4];
            const float4 vv = *(const float4*)&Vg[(size_t)j * DD + c4];
            const int o = r * AST + c4;
            *(float2*)&Ks[o]     = make_float2(kv.x, kv.y);
            *(float2*)&Ks[o + 2] = make_float2(kv.z, kv.w);
            *(float2*)&Vs[o]     = make_float2(vv.x, vv.y);
            *(float2*)&Vs[o + 2] = make_float2(vv.z, vv.w);
        }
    }
    for (int idx = tid; idx < BQ * 16; idx += 256) {
        const int r = idx >> 4, c4 = (idx & 15) * 4;
        const float4 qv = *(const float4*)&Qg[(size_t)r * DD + c4];
        const int o = r * AST + c4;
        *(float2*)&Qs[o]     = make_float2(qv.x, qv.y);
        *(float2*)&Qs[o + 2] = make_float2(qv.z, qv.w);
    }
    __syncthreads();

    float* pw = &ps[warp * 68];

    for (int qi = 0; qi < 8; ++qi) {
        const int qq = warp * 8 + qi;
        const int i  = q0 + qq;
        const int jlo = max(0, i - 32);
        const int jhi = min(SS - 1, i + 32);
        const int n   = jhi - jlo + 1;
        const int rbase = jlo - jbase;

        const float* Qr = &Qs[qq * AST];
        const float* K0 = &Ks[(rbase + lane) * AST];
        const float* K1 = &Ks[(rbase + lane + 32) * AST];
        const float* K2 = &Ks[(rbase + 64) * AST];

        float s0 = 0.f, s1 = 0.f, s2 = 0.f;
#pragma unroll
        for (int d = 0; d < 64; d += 2) {
            const float2 q2 = *(const float2*)&Qr[d];
            const float2 k0 = *(const float2*)&K0[d];
            const float2 k1 = *(const float2*)&K1[d];
            const float2 k2 = *(const float2*)&K2[d];
            s0 = fmaf(q2.x, k0.x, fmaf(q2.y, k0.y, s0));
            s1 = fmaf(q2.x, k1.x, fmaf(q2.y, k1.y, s1));
            s2 = fmaf(q2.x, k2.x, fmaf(q2.y, k2.y, s2));
        }
        s0 *= 0.125f; s1 *= 0.125f; s2 *= 0.125f;

        const bool v1 = (lane + 32) < n;
        const bool v2 = (n == 65);

        float m = s0;
        if (v1) m = fmaxf(m, s1);
        if (v2) m = fmaxf(m, s2);
#pragma unroll
        for (int off = 16; off; off >>= 1) m = fmaxf(m, __shfl_xor_sync(0xffffffffu, m, off));

        const float e0 = __expf(s0 - m);
        const float e1 = v1 ? __expf(s1 - m) : 0.f;
        const float e2 = v2 ? __expf(s2 - m) : 0.f;
        float ssum = e0 + e1 + ((lane == 0) ? e2 : 0.f);
#pragma unroll
        for (int off = 16; off; off >>= 1) ssum += __shfl_xor_sync(0xffffffffu, ssum, off);
        const float inv = 1.f / ssum;

        pw[lane] = e0 * inv;
        if (v1) pw[lane + 32] = e1 * inv;
        if (lane == 0 && v2) pw[64] = e2 * inv;
        __syncwarp();

        if (attn_out) {
            float* rowp = attn_out + ((size_t)bh * SS + i) * SS + jlo;
            rowp[lane] = e0 * inv;
            if (v1) rowp[lane + 32] = e1 * inv;
            if (lane == 0 && v2) rowp[64] = e2 * inv;
        }

        float a0 = 0.f, a1 = 0.f;
        const float* Vr = &Vs[rbase * AST];
        for (int jj = 0; jj < n; ++jj) {
            const float p = pw[jj];
            a0 = fmaf(p, Vr[lane], a0);
            a1 = fmaf(p, Vr[lane + 32], a1);
            Vr += AST;
        }

        const size_t co = ((size_t)(b * SS + i)) * DD + h * 64;
        hsplit(a0, g_Chi[co + lane],      g_Clo[co + lane]);
        hsplit(a1, g_Chi[co + lane + 32], g_Clo[co + lane + 32]);
        __syncwarp();
    }
}

// ---------------------------------------------------------------------------
extern "C" void kernel_launch(void* const* d_in, const int* in_sizes, int n_in,
                              void* d_out, int out_size)
{
    const float* q  = (const float*)d_in[0];
    const float* wq = (const float*)d_in[1];
    const float* wk = (const float*)d_in[2];
    const float* wv = (const float*)d_in[3];
    const float* wo = (const float*)d_in[4];
    const float* bo = (const float*)d_in[5];
    float* out = (float*)d_out;

    const size_t out_elems  = (size_t)BB * SS * DD;
    const bool   write_attn = (size_t)out_size > out_elems;
    float* attn = out + out_elems;

    static cudaStream_t s2 = nullptr;
    static cudaEvent_t evF = nullptr, evJ = nullptr;
    static int nsm = 0;
    if (!s2) {
        cudaStreamCreateWithFlags(&s2, cudaStreamNonBlocking);
        cudaEventCreateWithFlags(&evF, cudaEventDisableTiming);
        cudaEventCreateWithFlags(&evJ, cudaEventDisableTiming);
        cudaDeviceGetAttribute(&nsm, cudaDevAttrMultiProcessorCount, 0);
        if (nsm <= 0) nsm = 148;
        cudaFuncSetAttribute(qkv_p,    cudaFuncAttributeMaxDynamicSharedMemorySize, GEMM_SMEM);
        cudaFuncSetAttribute(out_p,    cudaFuncAttributeMaxDynamicSharedMemorySize, GEMM_SMEM);
        cudaFuncSetAttribute(attn_blk, cudaFuncAttributeMaxDynamicSharedMemorySize, ATT_SMEM);
    }

    if (write_attn) {
        cudaEventRecord(evF, 0);
        cudaStreamWaitEvent(s2, evF, 0);
        cudaMemsetAsync(attn, 0, (size_t)BB * HH * SS * SS * sizeof(float), s2);
        cudaEventRecord(evJ, s2);
    }

    // 1) split q + weights into fp16 hi / scaled-lo
    split_kernel<<<8192, 256>>>(q, wq, wk, wv, wo);

    // 2) QKV projections (persistent tiles)
    qkv_p<<<nsm, 256, GEMM_SMEM>>>();

    if (write_attn) cudaStreamWaitEvent(0, evJ, 0);

    // 3) local attention, writes split context + band
    dim3 ga(SS / BQ, BB * HH);
    attn_blk<<<ga, 256, ATT_SMEM>>>(write_attn ? attn : nullptr);

    // 4) output projection + bias (persistent tiles)
    out_p<<<nsm, 256, GEMM_SMEM>>>(bo, out);
}

// round 7
// speedup vs baseline: 1.2089x; 1.2089x over previous
#include <cuda_runtime.h>
#include <cuda_bf16.h>
#include <cuda_fp16.h>
#include <cstdint>

#define BB 2
#define SS 2048
#define DD 1024
#define HH 16
#define MM (BB*SS)             // 4096

// GEMM tiling: 128x128 tile, K-chunk 32 (64B rows, SW64-style swizzle)
#define TM 128
#define TN 128
#define KC 32
#define NCH (DD/KC)            // 32
#define NSTAGE 3
#define ARR_BYTES 8192         // 128 rows x 64B
#define STAGE_BYTES 32768
#define OFF_AH 0
#define OFF_AU 8192
#define OFF_BH 16384
#define OFF_BU 24576
#define GEMM_SMEM (NSTAGE*STAGE_BYTES)   // 98304

// Karatsuba combine: C = (1 - 2^-6) * acc_hh + acc_uu
#define C_MAIN 0.984375f

// Attention tiling
#define BQ 64
#define AROWS 128
#define AST 66
#define ATT_SMEM ((AROWS*AST*2 + BQ*AST + 8*68)*4)   // 86656 B

// ---------------------------------------------------------------------------
// Scratch (device globals: allocation-free rule)
// ---------------------------------------------------------------------------
__device__ float g_Q[(size_t)MM * DD];
__device__ float g_K[(size_t)MM * DD];
__device__ float g_V[(size_t)MM * DD];
__device__ __half g_Ah[(size_t)MM * DD];
__device__ __half g_Au[(size_t)MM * DD];
__device__ __half g_Wh[(size_t)4 * DD * DD];   // wq,wk,wv,wo
__device__ __half g_Wu[(size_t)4 * DD * DD];
__device__ __half g_Ch[(size_t)MM * DD];
__device__ __half g_Cu[(size_t)MM * DD];

// ---------------------------------------------------------------------------
// Helpers
// ---------------------------------------------------------------------------
__device__ __forceinline__ uint32_t smem_u32(const void* p) {
    uint32_t a;
    asm("{ .reg .u64 t; cvta.to.shared.u64 t, %1; cvt.u32.u64 %0, t; }"
        : "=r"(a) : "l"(p));
    return a;
}

__device__ __forceinline__ void cpasync16(uint32_t dst, const void* src) {
    asm volatile("cp.async.cg.shared.global [%0], [%1], 16;"
                 :: "r"(dst), "l"(src));
}
#define CP_COMMIT() asm volatile("cp.async.commit_group;" ::: "memory")
#define CP_WAIT1()  asm volatile("cp.async.wait_group 1;" ::: "memory")
#define CP_WAIT0()  asm volatile("cp.async.wait_group 0;" ::: "memory")

__device__ __forceinline__ void ldm4(uint32_t* r, uint32_t addr) {
    asm volatile("ldmatrix.sync.aligned.m8n8.x4.shared.b16 {%0,%1,%2,%3}, [%4];"
                 : "=r"(r[0]), "=r"(r[1]), "=r"(r[2]), "=r"(r[3]) : "r"(addr));
}

__device__ __forceinline__ void mma_f32(float* c, const uint32_t* a,
                                        uint32_t b0, uint32_t b1) {
    asm volatile(
        "mma.sync.aligned.m16n8k16.row.col.f32.f16.f16.f32 "
        "{%0,%1,%2,%3}, {%4,%5,%6,%7}, {%8,%9}, {%0,%1,%2,%3};"
        : "+f"(c[0]), "+f"(c[1]), "+f"(c[2]), "+f"(c[3])
        : "r"(a[0]), "r"(a[1]), "r"(a[2]), "r"(a[3]), "r"(b0), "r"(b1));
}

// x -> H = fp16(x), U = fp16(2^-3*H + 2^3*(x-H))
__device__ __forceinline__ void ksplit(float x, __half& h, __half& u) {
    h = __float2half_rn(x);
    const float hf = __half2float(h);
    u = __float2half_rn(fmaf(0.125f, hf, 8.0f * (x - hf)));
}

// ---------------------------------------------------------------------------
// Split pass: q + 4 weights -> fp16 H / U
// ---------------------------------------------------------------------------
__global__ void __launch_bounds__(256) split_kernel(const float* __restrict__ q,
                                                    const float* __restrict__ wq,
                                                    const float* __restrict__ wk,
                                                    const float* __restrict__ wv,
                                                    const float* __restrict__ wo)
{
    const size_t i4 = (size_t)blockIdx.x * 256 + threadIdx.x;
    const float* src;
    __half *dh, *du;
    size_t e;
    if (i4 < 1048576) {
        src = q; e = i4;
        dh = g_Ah; du = g_Au;
    } else {
        const size_t r = i4 - 1048576;
        const int w = (int)(r >> 18);
        e = r & 262143;
        src = (w == 0) ? wq : (w == 1) ? wk : (w == 2) ? wv : wo;
        dh = g_Wh + (size_t)w * DD * DD;
        du = g_Wu + (size_t)w * DD * DD;
    }
    const float4 v = ((const float4*)src)[e];
    __half h[4], u[4];
    ksplit(v.x, h[0], u[0]); ksplit(v.y, h[1], u[1]);
    ksplit(v.z, h[2], u[2]); ksplit(v.w, h[3], u[3]);
    *(ushort4*)(dh + e * 4) = make_ushort4(*(unsigned short*)&h[0], *(unsigned short*)&h[1],
                                           *(unsigned short*)&h[2], *(unsigned short*)&h[3]);
    *(ushort4*)(du + e * 4) = make_ushort4(*(unsigned short*)&u[0], *(unsigned short*)&u[1],
                                           *(unsigned short*)&u[2], *(unsigned short*)&u[3]);
}

// ---------------------------------------------------------------------------
// fp16 Karatsuba GEMM: C = (1-2^-6)*Sum(Ah*Bh) + Sum(Au*Bu)  (+bias)
//   Tile 128x128, 256 thr, 8 warps (2M x 4N), warp subtile 64x32.
// ---------------------------------------------------------------------------
__device__ __forceinline__ void gemm_body(const __half* __restrict__ Ah,
                                          const __half* __restrict__ Au,
                                          const __half* __restrict__ Wh,
                                          const __half* __restrict__ Wu,
                                          float* __restrict__ C,
                                          const float* __restrict__ bias)
{
    extern __shared__ char dsm[];
    const uint32_t sb = smem_u32(dsm);
    const int tid  = threadIdx.x;
    const int wid  = tid >> 5;
    const int lane = tid & 31;
    const int wm   = wid >> 2;        // 0..1
    const int wn   = wid & 3;         // 0..3
    const int brow = blockIdx.y * TM;
    const int bcol = blockIdx.x * TN;

    const __half* Abase[2] = { Ah + (size_t)brow * DD, Au + (size_t)brow * DD };
    const __half* Bbase[2] = { Wh + (size_t)bcol * DD, Wu + (size_t)bcol * DD };

    float acc[4][4][4];    // main (hh)
    float acc2[4][4][4];   // combo (uu)
#pragma unroll
    for (int a = 0; a < 4; ++a)
#pragma unroll
        for (int b = 0; b < 4; ++b)
#pragma unroll
            for (int c = 0; c < 4; ++c) { acc[a][b][c] = 0.f; acc2[a][b][c] = 0.f; }

    auto issue = [&](int kc, int stg) {
#pragma unroll
        for (int arr = 0; arr < 4; ++arr) {
            const __half* g = (arr < 2) ? Abase[arr] : Bbase[arr - 2];
            const uint32_t sdst = sb + stg * STAGE_BYTES + arr * ARR_BYTES;
#pragma unroll
            for (int it = 0; it < 2; ++it) {
                const int id = tid + it * 256;     // 0..511
                const int r = id >> 2, c = id & 3;
                const void* src = g + (size_t)r * DD + kc * KC + c * 8;
                const uint32_t dst = sdst + r * 64 + ((c ^ ((r >> 1) & 3)) << 4);
                cpasync16(dst, src);
            }
        }
        CP_COMMIT();
    };

    issue(0, 0);
    issue(1, 1);

    for (int kc = 0; kc < NCH; ++kc) {
        if (kc + 1 < NCH) CP_WAIT1(); else CP_WAIT0();
        __syncthreads();
        if (kc + 2 < NCH) issue(kc + 2, (kc + 2) % NSTAGE);

        const uint32_t st = sb + (kc % NSTAGE) * STAGE_BYTES;
#pragma unroll
        for (int kk = 0; kk < 2; ++kk) {           // 2 x k16 per chunk
            const int c16 = kk * 2 + (lane >> 4);  // 16B chunk 0..3
            uint32_t aoff[4], boff[2];
#pragma unroll
            for (int mi = 0; mi < 4; ++mi) {
                const int row = wm * 64 + mi * 16 + (lane & 15);
                aoff[mi] = row * 64 + ((c16 ^ ((row >> 1) & 3)) << 4);
            }
#pragma unroll
            for (int nb = 0; nb < 2; ++nb) {
                const int row = wn * 32 + nb * 16 + (lane & 15);
                boff[nb] = row * 64 + ((c16 ^ ((row >> 1) & 3)) << 4);
            }
            uint32_t ah[4][4], bh[2][4];
#pragma unroll
            for (int mi = 0; mi < 4; ++mi) ldm4(ah[mi], st + OFF_AH + aoff[mi]);
#pragma unroll
            for (int nb = 0; nb < 2; ++nb) ldm4(bh[nb], st + OFF_BH + boff[nb]);
            // main term while U fragments load below
#pragma unroll
            for (int mi = 0; mi < 4; ++mi)
#pragma unroll
                for (int ni = 0; ni < 4; ++ni) {
                    const int nb = ni >> 1, s = ni & 1;
                    mma_f32(acc[mi][ni], ah[mi], bh[nb][s], bh[nb][s + 2]);
                }
            uint32_t au[4][4], bu[2][4];
#pragma unroll
            for (int mi = 0; mi < 4; ++mi) ldm4(au[mi], st + OFF_AU + aoff[mi]);
#pragma unroll
            for (int nb = 0; nb < 2; ++nb) ldm4(bu[nb], st + OFF_BU + boff[nb]);
#pragma unroll
            for (int mi = 0; mi < 4; ++mi)
#pragma unroll
                for (int ni = 0; ni < 4; ++ni) {
                    const int nb = ni >> 1, s = ni & 1;
                    mma_f32(acc2[mi][ni], au[mi], bu[nb][s], bu[nb][s + 2]);
                }
        }
    }

    // Epilogue: C = (1-2^-6)*acc + acc2 (+bias)
#pragma unroll
    for (int mi = 0; mi < 4; ++mi) {
        const int row = brow + wm * 64 + mi * 16 + (lane >> 2);
#pragma unroll
        for (int ni = 0; ni < 4; ++ni) {
            const int col = bcol + wn * 32 + ni * 8 + (lane & 3) * 2;
            float2 v0 = make_float2(fmaf(C_MAIN, acc[mi][ni][0], acc2[mi][ni][0]),
                                    fmaf(C_MAIN, acc[mi][ni][1], acc2[mi][ni][1]));
            float2 v1 = make_float2(fmaf(C_MAIN, acc[mi][ni][2], acc2[mi][ni][2]),
                                    fmaf(C_MAIN, acc[mi][ni][3], acc2[mi][ni][3]));
            if (bias) {
                const float b0 = bias[col], b1 = bias[col + 1];
                v0.x += b0; v0.y += b1; v1.x += b0; v1.y += b1;
            }
            *(float2*)&C[(size_t)row * DD + col]       = v0;
            *(float2*)&C[(size_t)(row + 8) * DD + col] = v1;
        }
    }
}

__global__ void __launch_bounds__(256, 1) qkv_bf()
{
    const int z = blockIdx.z;
    float* Cc = (z == 0) ? g_Q : ((z == 1) ? g_K : g_V);
    gemm_body(g_Ah, g_Au,
              g_Wh + (size_t)z * DD * DD, g_Wu + (size_t)z * DD * DD,
              Cc, nullptr);
}

__global__ void __launch_bounds__(256, 1) out_bf(const float* __restrict__ bo,
                                                 float* __restrict__ out)
{
    gemm_body(g_Ch, g_Cu,
              g_Wh + (size_t)3 * DD * DD, g_Wu + (size_t)3 * DD * DD,
              out, bo);
}

// ---------------------------------------------------------------------------
// Local-window attention, lane-per-key. Block = 64 queries x (b,h).
// ---------------------------------------------------------------------------
__global__ void __launch_bounds__(256) attn_blk(float* __restrict__ attn_out)
{
    extern __shared__ float s[];
    float* Ks = s;
    float* Vs = Ks + AROWS * AST;
    float* Qs = Vs + AROWS * AST;
    float* ps = Qs + BQ * AST;

    const int tid  = threadIdx.x;
    const int warp = tid >> 5;
    const int lane = tid & 31;
    const int q0   = blockIdx.x * BQ;
    const int bh   = blockIdx.y;
    const int h    = bh & (HH - 1);
    const int b    = bh >> 4;
    const int jbase = q0 - 32;

    const float* Kg = g_K + (size_t)b * SS * DD + h * 64;
    const float* Vg = g_V + (size_t)b * SS * DD + h * 64;
    const float* Qg = g_Q + ((size_t)(b * SS + q0)) * DD + h * 64;

    for (int idx = tid; idx < AROWS * 16; idx += 256) {
        const int r = idx >> 4, c4 = (idx & 15) * 4;
        const int j = jbase + r;
        if (j >= 0 && j < SS) {
            const float4 kv = *(const float4*)&Kg[(size_t)j * DD + c4];
            const float4 vv = *(const float4*)&Vg[(size_t)j * DD + c4];
            const int o = r * AST + c4;
            *(float2*)&Ks[o]     = make_float2(kv.x, kv.y);
            *(float2*)&Ks[o + 2] = make_float2(kv.z, kv.w);
            *(float2*)&Vs[o]     = make_float2(vv.x, vv.y);
            *(float2*)&Vs[o + 2] = make_float2(vv.z, vv.w);
        }
    }
    for (int idx = tid; idx < BQ * 16; idx += 256) {
        const int r = idx >> 4, c4 = (idx & 15) * 4;
        const float4 qv = *(const float4*)&Qg[(size_t)r * DD + c4];
        const int o = r * AST + c4;
        *(float2*)&Qs[o]     = make_float2(qv.x, qv.y);
        *(float2*)&Qs[o + 2] = make_float2(qv.z, qv.w);
    }
    __syncthreads();

    float* pw = &ps[warp * 68];

    for (int qi = 0; qi < 8; ++qi) {
        const int qq = warp * 8 + qi;
        const int i  = q0 + qq;
        const int jlo = max(0, i - 32);
        const int jhi = min(SS - 1, i + 32);
        const int n   = jhi - jlo + 1;
        const int rbase = jlo - jbase;

        const float* Qr = &Qs[qq * AST];
        const float* K0 = &Ks[(rbase + lane) * AST];
        const float* K1 = &Ks[(rbase + lane + 32) * AST];
        const float* K2 = &Ks[(rbase + 64) * AST];

        float s0 = 0.f, s1 = 0.f, s2 = 0.f;
#pragma unroll
        for (int d = 0; d < 64; d += 2) {
            const float2 q2 = *(const float2*)&Qr[d];
            const float2 k0 = *(const float2*)&K0[d];
            const float2 k1 = *(const float2*)&K1[d];
            const float2 k2 = *(const float2*)&K2[d];
            s0 = fmaf(q2.x, k0.x, fmaf(q2.y, k0.y, s0));
            s1 = fmaf(q2.x, k1.x, fmaf(q2.y, k1.y, s1));
            s2 = fmaf(q2.x, k2.x, fmaf(q2.y, k2.y, s2));
        }
        s0 *= 0.125f; s1 *= 0.125f; s2 *= 0.125f;

        const bool v1 = (lane + 32) < n;
        const bool v2 = (n == 65);

        float m = s0;
        if (v1) m = fmaxf(m, s1);
        if (v2) m = fmaxf(m, s2);
#pragma unroll
        for (int off = 16; off; off >>= 1) m = fmaxf(m, __shfl_xor_sync(0xffffffffu, m, off));

        const float e0 = __expf(s0 - m);
        const float e1 = v1 ? __expf(s1 - m) : 0.f;
        const float e2 = v2 ? __expf(s2 - m) : 0.f;
        float ssum = e0 + e1 + ((lane == 0) ? e2 : 0.f);
#pragma unroll
        for (int off = 16; off; off >>= 1) ssum += __shfl_xor_sync(0xffffffffu, ssum, off);
        const float inv = 1.f / ssum;

        pw[lane] = e0 * inv;
        if (v1) pw[lane + 32] = e1 * inv;
        if (lane == 0 && v2) pw[64] = e2 * inv;
        __syncwarp();

        if (attn_out) {
            float* rowp = attn_out + ((size_t)bh * SS + i) * SS + jlo;
            rowp[lane] = e0 * inv;
            if (v1) rowp[lane + 32] = e1 * inv;
            if (lane == 0 && v2) rowp[64] = e2 * inv;
        }

        float a0 = 0.f, a1 = 0.f;
        const float* Vr = &Vs[rbase * AST];
        for (int jj = 0; jj < n; ++jj) {
            const float p = pw[jj];
            a0 = fmaf(p, Vr[lane], a0);
            a1 = fmaf(p, Vr[lane + 32], a1);
            Vr += AST;
        }

        const size_t co = ((size_t)(b * SS + i)) * DD + h * 64;
        ksplit(a0, g_Ch[co + lane],      g_Cu[co + lane]);
        ksplit(a1, g_Ch[co + lane + 32], g_Cu[co + lane + 32]);
        __syncwarp();
    }
}

// ---------------------------------------------------------------------------
extern "C" void kernel_launch(void* const* d_in, const int* in_sizes, int n_in,
                              void* d_out, int out_size)
{
    const float* q  = (const float*)d_in[0];
    const float* wq = (const float*)d_in[1];
    const float* wk = (const float*)d_in[2];
    const float* wv = (const float*)d_in[3];
    const float* wo = (const float*)d_in[4];
    const float* bo = (const float*)d_in[5];
    float* out = (float*)d_out;

    const size_t out_elems  = (size_t)BB * SS * DD;
    const bool   write_attn = (size_t)out_size > out_elems;
    float* attn = out + out_elems;

    static cudaStream_t s2 = nullptr;
    static cudaEvent_t evF = nullptr, evJ = nullptr;
    if (!s2) {
        cudaStreamCreateWithFlags(&s2, cudaStreamNonBlocking);
        cudaEventCreateWithFlags(&evF, cudaEventDisableTiming);
        cudaEventCreateWithFlags(&evJ, cudaEventDisableTiming);
        cudaFuncSetAttribute(qkv_bf,   cudaFuncAttributeMaxDynamicSharedMemorySize, GEMM_SMEM);
        cudaFuncSetAttribute(out_bf,   cudaFuncAttributeMaxDynamicSharedMemorySize, GEMM_SMEM);
        cudaFuncSetAttribute(attn_blk, cudaFuncAttributeMaxDynamicSharedMemorySize, ATT_SMEM);
    }

    if (write_attn) {
        cudaEventRecord(evF, 0);
        cudaStreamWaitEvent(s2, evF, 0);
        cudaMemsetAsync(attn, 0, (size_t)BB * HH * SS * SS * sizeof(float), s2);
        cudaEventRecord(evJ, s2);
    }

    // 1) split q + weights into fp16 H / U
    split_kernel<<<8192, 256>>>(q, wq, wk, wv, wo);

    // 2) QKV projections (Karatsuba 2-MMA)
    dim3 gq3(DD / TN, MM / TM, 3);
    qkv_bf<<<gq3, 256, GEMM_SMEM>>>();

    if (write_attn) cudaStreamWaitEvent(0, evJ, 0);

    // 3) local attention, writes split context + band
    dim3 ga(SS / BQ, BB * HH);
    attn_blk<<<ga, 256, ATT_SMEM>>>(write_attn ? attn : nullptr);

    // 4) output projection + bias (Karatsuba 2-MMA)
    dim3 go(DD / TN, MM / TM, 1);
    out_bf<<<go, 256, GEMM_SMEM>>>(bo, out);
}

// round 9
// speedup vs baseline: 1.3238x; 1.0950x over previous
#include <cuda_runtime.h>
#include <cuda_bf16.h>
#include <cuda_fp16.h>
#include <cstdint>

#define BB 2
#define SS 2048
#define DD 1024
#define HH 16
#define MM (BB*SS)             // 4096

// GEMM tiling: 128x128 tile, K-chunk 64 (128B rows, SW128 swizzle)
#define TM 128
#define TN 128
#define KC 64
#define NCH (DD/KC)            // 16
#define NSTAGE 3               // MUST be >=3: issue(kc+2) while reading kc
#define ARR_BYTES 16384        // 128 rows x 128B
#define STAGE_BYTES 65536
#define OFF_AH 0
#define OFF_AU 16384
#define OFF_BH 32768
#define OFF_BU 49152
#define GEMM_SMEM (NSTAGE*STAGE_BYTES)   // 196608

// Karatsuba combine: C = (1 - 2^-6) * acc_hh + acc_uu
#define C_MAIN 0.984375f

// Attention tiling
#define BQ 64
#define AROWS 128
#define AST 66
#define ATT_SMEM ((AROWS*AST*2 + BQ*AST + 8*68)*4)   // 86656 B

// ---------------------------------------------------------------------------
// Scratch (device globals: allocation-free rule)
// ---------------------------------------------------------------------------
__device__ float g_Q[(size_t)MM * DD];
__device__ float g_K[(size_t)MM * DD];
__device__ float g_V[(size_t)MM * DD];
__device__ __half g_Ah[(size_t)MM * DD];
__device__ __half g_Au[(size_t)MM * DD];
__device__ __half g_Wh[(size_t)4 * DD * DD];   // wq,wk,wv,wo
__device__ __half g_Wu[(size_t)4 * DD * DD];
__device__ __half g_Ch[(size_t)MM * DD];
__device__ __half g_Cu[(size_t)MM * DD];

// ---------------------------------------------------------------------------
// Helpers
// ---------------------------------------------------------------------------
__device__ __forceinline__ uint32_t smem_u32(const void* p) {
    uint32_t a;
    asm("{ .reg .u64 t; cvta.to.shared.u64 t, %1; cvt.u32.u64 %0, t; }"
        : "=r"(a) : "l"(p));
    return a;
}

__device__ __forceinline__ void cpasync16(uint32_t dst, const void* src) {
    asm volatile("cp.async.cg.shared.global [%0], [%1], 16;"
                 :: "r"(dst), "l"(src));
}
#define CP_COMMIT() asm volatile("cp.async.commit_group;" ::: "memory")
#define CP_WAIT1()  asm volatile("cp.async.wait_group 1;" ::: "memory")
#define CP_WAIT0()  asm volatile("cp.async.wait_group 0;" ::: "memory")

__device__ __forceinline__ void ldm4(uint32_t* r, uint32_t addr) {
    asm volatile("ldmatrix.sync.aligned.m8n8.x4.shared.b16 {%0,%1,%2,%3}, [%4];"
                 : "=r"(r[0]), "=r"(r[1]), "=r"(r[2]), "=r"(r[3]) : "r"(addr));
}

__device__ __forceinline__ void mma_f32(float* c, const uint32_t* a,
                                        uint32_t b0, uint32_t b1) {
    asm volatile(
        "mma.sync.aligned.m16n8k16.row.col.f32.f16.f16.f32 "
        "{%0,%1,%2,%3}, {%4,%5,%6,%7}, {%8,%9}, {%0,%1,%2,%3};"
        : "+f"(c[0]), "+f"(c[1]), "+f"(c[2]), "+f"(c[3])
        : "r"(a[0]), "r"(a[1]), "r"(a[2]), "r"(a[3]), "r"(b0), "r"(b1));
}

// x -> H = fp16(x), U = fp16(2^-3*H + 2^3*(x-H))
__device__ __forceinline__ void ksplit(float x, __half& h, __half& u) {
    h = __float2half_rn(x);
    const float hf = __half2float(h);
    u = __float2half_rn(fmaf(0.125f, hf, 8.0f * (x - hf)));
}

// ---------------------------------------------------------------------------
// Split pass: q + 4 weights -> fp16 H / U
// ---------------------------------------------------------------------------
__global__ void __launch_bounds__(256) split_kernel(const float* __restrict__ q,
                                                    const float* __restrict__ wq,
                                                    const float* __restrict__ wk,
                                                    const float* __restrict__ wv,
                                                    const float* __restrict__ wo)
{
    const size_t i4 = (size_t)blockIdx.x * 256 + threadIdx.x;
    const float* src;
    __half *dh, *du;
    size_t e;
    if (i4 < 1048576) {
        src = q; e = i4;
        dh = g_Ah; du = g_Au;
    } else {
        const size_t r = i4 - 1048576;
        const int w = (int)(r >> 18);
        e = r & 262143;
        src = (w == 0) ? wq : (w == 1) ? wk : (w == 2) ? wv : wo;
        dh = g_Wh + (size_t)w * DD * DD;
        du = g_Wu + (size_t)w * DD * DD;
    }
    const float4 v = ((const float4*)src)[e];
    __half h[4], u[4];
    ksplit(v.x, h[0], u[0]); ksplit(v.y, h[1], u[1]);
    ksplit(v.z, h[2], u[2]); ksplit(v.w, h[3], u[3]);
    *(ushort4*)(dh + e * 4) = make_ushort4(*(unsigned short*)&h[0], *(unsigned short*)&h[1],
                                           *(unsigned short*)&h[2], *(unsigned short*)&h[3]);
    *(ushort4*)(du + e * 4) = make_ushort4(*(unsigned short*)&u[0], *(unsigned short*)&u[1],
                                           *(unsigned short*)&u[2], *(unsigned short*)&u[3]);
}

// ---------------------------------------------------------------------------
// fp16 Karatsuba GEMM: C = (1-2^-6)*Sum(Ah*Bh) + Sum(Au*Bu)  (+bias)
//   Tile 128x128, 256 thr, 8 warps (2M x 4N), warp subtile 64x32.
//   KC=64, 3-stage cp.async pipeline; per-k16 all-LDSM-then-MMA issue order.
// ---------------------------------------------------------------------------
__device__ __forceinline__ void gemm_body(const __half* __restrict__ Ah,
                                          const __half* __restrict__ Au,
                                          const __half* __restrict__ Wh,
                                          const __half* __restrict__ Wu,
                                          float* __restrict__ C,
                                          const float* __restrict__ bias)
{
    extern __shared__ char dsm[];
    const uint32_t sb = smem_u32(dsm);
    const int tid  = threadIdx.x;
    const int wid  = tid >> 5;
    const int lane = tid & 31;
    const int wm   = wid >> 2;        // 0..1
    const int wn   = wid & 3;         // 0..3
    const int brow = blockIdx.y * TM;
    const int bcol = blockIdx.x * TN;

    const __half* Abase[2] = { Ah + (size_t)brow * DD, Au + (size_t)brow * DD };
    const __half* Bbase[2] = { Wh + (size_t)bcol * DD, Wu + (size_t)bcol * DD };

    float acc[4][4][4];    // main (hh)
    float acc2[4][4][4];   // combo (uu)
#pragma unroll
    for (int a = 0; a < 4; ++a)
#pragma unroll
        for (int b = 0; b < 4; ++b)
#pragma unroll
            for (int c = 0; c < 4; ++c) { acc[a][b][c] = 0.f; acc2[a][b][c] = 0.f; }

    auto issue = [&](int kc, int stg) {
#pragma unroll
        for (int arr = 0; arr < 4; ++arr) {
            const __half* g = (arr < 2) ? Abase[arr] : Bbase[arr - 2];
            const uint32_t sdst = sb + stg * STAGE_BYTES + arr * ARR_BYTES;
#pragma unroll
            for (int it = 0; it < 4; ++it) {
                const int id = tid + it * 256;     // 0..1023
                const int r = id >> 3, c = id & 7;
                const void* src = g + (size_t)r * DD + kc * KC + c * 8;
                const uint32_t dst = sdst + r * 128 + ((c ^ (r & 7)) << 4);
                cpasync16(dst, src);
            }
        }
        CP_COMMIT();
    };

    issue(0, 0);
    issue(1, 1);

    for (int kc = 0; kc < NCH; ++kc) {
        if (kc + 1 < NCH) CP_WAIT1(); else CP_WAIT0();
        __syncthreads();
        if (kc + 2 < NCH) issue(kc + 2, (kc + 2) % NSTAGE);

        const uint32_t st = sb + (kc % NSTAGE) * STAGE_BYTES;
#pragma unroll
        for (int kk = 0; kk < 4; ++kk) {           // 4 x k16 per chunk
            const int c16 = kk * 2 + (lane >> 4);  // 16B chunk 0..7
            uint32_t aoff[4], boff[2];
#pragma unroll
            for (int mi = 0; mi < 4; ++mi) {
                const int row = wm * 64 + mi * 16 + (lane & 15);
                aoff[mi] = row * 128 + ((c16 ^ (row & 7)) << 4);
            }
#pragma unroll
            for (int nb = 0; nb < 2; ++nb) {
                const int row = wn * 32 + nb * 16 + (lane & 15);
                boff[nb] = row * 128 + ((c16 ^ (row & 7)) << 4);
            }
            // issue ALL fragment loads (H then U) before any MMA:
            // H MMAs below cover the U ldmatrix latency.
            uint32_t ah[4][4], bh[2][4], au[4][4], bu[2][4];
#pragma unroll
            for (int mi = 0; mi < 4; ++mi) ldm4(ah[mi], st + OFF_AH + aoff[mi]);
#pragma unroll
            for (int nb = 0; nb < 2; ++nb) ldm4(bh[nb], st + OFF_BH + boff[nb]);
#pragma unroll
            for (int mi = 0; mi < 4; ++mi) ldm4(au[mi], st + OFF_AU + aoff[mi]);
#pragma unroll
            for (int nb = 0; nb < 2; ++nb) ldm4(bu[nb], st + OFF_BU + boff[nb]);
#pragma unroll
            for (int mi = 0; mi < 4; ++mi)
#pragma unroll
                for (int ni = 0; ni < 4; ++ni) {
                    const int nb = ni >> 1, s = ni & 1;
                    mma_f32(acc[mi][ni], ah[mi], bh[nb][s], bh[nb][s + 2]);
                }
#pragma unroll
            for (int mi = 0; mi < 4; ++mi)
#pragma unroll
                for (int ni = 0; ni < 4; ++ni) {
                    const int nb = ni >> 1, s = ni & 1;
                    mma_f32(acc2[mi][ni], au[mi], bu[nb][s], bu[nb][s + 2]);
                }
        }
    }

    // Epilogue: C = (1-2^-6)*acc + acc2 (+bias)
#pragma unroll
    for (int mi = 0; mi < 4; ++mi) {
        const int row = brow + wm * 64 + mi * 16 + (lane >> 2);
#pragma unroll
        for (int ni = 0; ni < 4; ++ni) {
            const int col = bcol + wn * 32 + ni * 8 + (lane & 3) * 2;
            float2 v0 = make_float2(fmaf(C_MAIN, acc[mi][ni][0], acc2[mi][ni][0]),
                                    fmaf(C_MAIN, acc[mi][ni][1], acc2[mi][ni][1]));
            float2 v1 = make_float2(fmaf(C_MAIN, acc[mi][ni][2], acc2[mi][ni][2]),
                                    fmaf(C_MAIN, acc[mi][ni][3], acc2[mi][ni][3]));
            if (bias) {
                const float b0 = bias[col], b1 = bias[col + 1];
                v0.x += b0; v0.y += b1; v1.x += b0; v1.y += b1;
            }
            *(float2*)&C[(size_t)row * DD + col]       = v0;
            *(float2*)&C[(size_t)(row + 8) * DD + col] = v1;
        }
    }
}

__global__ void __launch_bounds__(256, 1) qkv_bf()
{
    const int z = blockIdx.z;
    float* Cc = (z == 0) ? g_Q : ((z == 1) ? g_K : g_V);
    gemm_body(g_Ah, g_Au,
              g_Wh + (size_t)z * DD * DD, g_Wu + (size_t)z * DD * DD,
              Cc, nullptr);
}

__global__ void __launch_bounds__(256, 1) out_bf(const float* __restrict__ bo,
                                                 float* __restrict__ out)
{
    gemm_body(g_Ch, g_Cu,
              g_Wh + (size_t)3 * DD * DD, g_Wu + (size_t)3 * DD * DD,
              out, bo);
}

// ---------------------------------------------------------------------------
// Local-window attention, lane-per-key. Block = 64 queries x (b,h).
// ---------------------------------------------------------------------------
__global__ void __launch_bounds__(256) attn_blk(float* __restrict__ attn_out)
{
    extern __shared__ float s[];
    float* Ks = s;
    float* Vs = Ks + AROWS * AST;
    float* Qs = Vs + AROWS * AST;
    float* ps = Qs + BQ * AST;

    const int tid  = threadIdx.x;
    const int warp = tid >> 5;
    const int lane = tid & 31;
    const int q0   = blockIdx.x * BQ;
    const int bh   = blockIdx.y;
    const int h    = bh & (HH - 1);
    const int b    = bh >> 4;
    const int jbase = q0 - 32;

    const float* Kg = g_K + (size_t)b * SS * DD + h * 64;
    const float* Vg = g_V + (size_t)b * SS * DD + h * 64;
    const float* Qg = g_Q + ((size_t)(b * SS + q0)) * DD + h * 64;

    for (int idx = tid; idx < AROWS * 16; idx += 256) {
        const int r = idx >> 4, c4 = (idx & 15) * 4;
        const int j = jbase + r;
        if (j >= 0 && j < SS) {
            const float4 kv = *(const float4*)&Kg[(size_t)j * DD + c4];
            const float4 vv = *(const float4*)&Vg[(size_t)j * DD + c4];
            const int o = r * AST + c4;
            *(float2*)&Ks[o]     = make_float2(kv.x, kv.y);
            *(float2*)&Ks[o + 2] = make_float2(kv.z, kv.w);
            *(float2*)&Vs[o]     = make_float2(vv.x, vv.y);
            *(float2*)&Vs[o + 2] = make_float2(vv.z, vv.w);
        }
    }
    for (int idx = tid; idx < BQ * 16; idx += 256) {
        const int r = idx >> 4, c4 = (idx & 15) * 4;
        const float4 qv = *(const float4*)&Qg[(size_t)r * DD + c4];
        const int o = r * AST + c4;
        *(float2*)&Qs[o]     = make_float2(qv.x, qv.y);
        *(float2*)&Qs[o + 2] = make_float2(qv.z, qv.w);
    }
    __syncthreads();

    float* pw = &ps[warp * 68];

    for (int qi = 0; qi < 8; ++qi) {
        const int qq = warp * 8 + qi;
        const int i  = q0 + qq;
        const int jlo = max(0, i - 32);
        const int jhi = min(SS - 1, i + 32);
        const int n   = jhi - jlo + 1;
        const int rbase = jlo - jbase;

        const float* Qr = &Qs[qq * AST];
        const float* K0 = &Ks[(rbase + lane) * AST];
        const float* K1 = &Ks[(rbase + lane + 32) * AST];
        const float* K2 = &Ks[(rbase + 64) * AST];

        float s0 = 0.f, s1 = 0.f, s2 = 0.f;
#pragma unroll
        for (int d = 0; d < 64; d += 2) {
            const float2 q2 = *(const float2*)&Qr[d];
            const float2 k0 = *(const float2*)&K0[d];
            const float2 k1 = *(const float2*)&K1[d];
            const float2 k2 = *(const float2*)&K2[d];
            s0 = fmaf(q2.x, k0.x, fmaf(q2.y, k0.y, s0));
            s1 = fmaf(q2.x, k1.x, fmaf(q2.y, k1.y, s1));
            s2 = fmaf(q2.x, k2.x, fmaf(q2.y, k2.y, s2));
        }
        s0 *= 0.125f; s1 *= 0.125f; s2 *= 0.125f;

        const bool v1 = (lane + 32) < n;
        const bool v2 = (n == 65);

        float m = s0;
        if (v1) m = fmaxf(m, s1);
        if (v2) m = fmaxf(m, s2);
#pragma unroll
        for (int off = 16; off; off >>= 1) m = fmaxf(m, __shfl_xor_sync(0xffffffffu, m, off));

        const float e0 = __expf(s0 - m);
        const float e1 = v1 ? __expf(s1 - m) : 0.f;
        const float e2 = v2 ? __expf(s2 - m) : 0.f;
        float ssum = e0 + e1 + ((lane == 0) ? e2 : 0.f);
#pragma unroll
        for (int off = 16; off; off >>= 1) ssum += __shfl_xor_sync(0xffffffffu, ssum, off);
        const float inv = 1.f / ssum;

        pw[lane] = e0 * inv;
        if (v1) pw[lane + 32] = e1 * inv;
        if (lane == 0 && v2) pw[64] = e2 * inv;
        __syncwarp();

        if (attn_out) {
            float* rowp = attn_out + ((size_t)bh * SS + i) * SS + jlo;
            rowp[lane] = e0 * inv;
            if (v1) rowp[lane + 32] = e1 * inv;
            if (lane == 0 && v2) rowp[64] = e2 * inv;
        }

        float a0 = 0.f, a1 = 0.f;
        const float* Vr = &Vs[rbase * AST];
        for (int jj = 0; jj < n; ++jj) {
            const float p = pw[jj];
            a0 = fmaf(p, Vr[lane], a0);
            a1 = fmaf(p, Vr[lane + 32], a1);
            Vr += AST;
        }

        const size_t co = ((size_t)(b * SS + i)) * DD + h * 64;
        ksplit(a0, g_Ch[co + lane],      g_Cu[co + lane]);
        ksplit(a1, g_Ch[co + lane + 32], g_Cu[co + lane + 32]);
        __syncwarp();
    }
}

// ---------------------------------------------------------------------------
extern "C" void kernel_launch(void* const* d_in, const int* in_sizes, int n_in,
                              void* d_out, int out_size)
{
    const float* q  = (const float*)d_in[0];
    const float* wq = (const float*)d_in[1];
    const float* wk = (const float*)d_in[2];
    const float* wv = (const float*)d_in[3];
    const float* wo = (const float*)d_in[4];
    const float* bo = (const float*)d_in[5];
    float* out = (float*)d_out;

    const size_t out_elems  = (size_t)BB * SS * DD;
    const bool   write_attn = (size_t)out_size > out_elems;
    float* attn = out + out_elems;

    static cudaStream_t s2 = nullptr;
    static cudaEvent_t evF = nullptr, evJ = nullptr;
    if (!s2) {
        cudaStreamCreateWithFlags(&s2, cudaStreamNonBlocking);
        cudaEventCreateWithFlags(&evF, cudaEventDisableTiming);
        cudaEventCreateWithFlags(&evJ, cudaEventDisableTiming);
        cudaFuncSetAttribute(qkv_bf,   cudaFuncAttributeMaxDynamicSharedMemorySize, GEMM_SMEM);
        cudaFuncSetAttribute(out_bf,   cudaFuncAttributeMaxDynamicSharedMemorySize, GEMM_SMEM);
        cudaFuncSetAttribute(attn_blk, cudaFuncAttributeMaxDynamicSharedMemorySize, ATT_SMEM);
    }

    if (write_attn) {
        cudaEventRecord(evF, 0);
        cudaStreamWaitEvent(s2, evF, 0);
        cudaMemsetAsync(attn, 0, (size_t)BB * HH * SS * SS * sizeof(float), s2);
        cudaEventRecord(evJ, s2);
    }

    // 1) split q + weights into fp16 H / U
    split_kernel<<<8192, 256>>>(q, wq, wk, wv, wo);

    // 2) QKV projections (Karatsuba 2-MMA)
    dim3 gq3(DD / TN, MM / TM, 3);
    qkv_bf<<<gq3, 256, GEMM_SMEM>>>();

    if (write_attn) cudaStreamWaitEvent(0, evJ, 0);

    // 3) local attention, writes split context + band
    dim3 ga(SS / BQ, BB * HH);
    attn_blk<<<ga, 256, ATT_SMEM>>>(write_attn ? attn : nullptr);

    // 4) output projection + bias (Karatsuba 2-MMA)
    dim3 go(DD / TN, MM / TM, 1);
    out_bf<<<go, 256, GEMM_SMEM>>>(bo, out);
}

// round 10
// speedup vs baseline: 1.3719x; 1.0363x over previous
#include <cuda_runtime.h>
#include <cuda_bf16.h>
#include <cuda_fp16.h>
#include <cstdint>

#define BB 2
#define SS 2048
#define DD 1024
#define HH 16
#define MM (BB*SS)             // 4096

// GEMM tiling: 128x128 tile, K-chunk 64 (128B rows, SW128 swizzle)
#define TM 128
#define TN 128
#define KC 64
#define NCH (DD/KC)            // 16
#define NSTAGE 3               // MUST be >=3: issue(kc+2) while reading kc
#define ARR_BYTES 16384        // 128 rows x 128B
#define STAGE_BYTES 65536
#define OFF_AH 0
#define OFF_AU 16384
#define OFF_BH 32768
#define OFF_BU 49152
#define GEMM_SMEM (NSTAGE*STAGE_BYTES)   // 196608

// Karatsuba combine: C = (1 - 2^-6) * acc_hh + acc_uu
#define C_MAIN 0.984375f

// Attention v2 tiling: block = 64 queries x 128-key window, register tiled
#define QSTRIDE 68             // Q row stride (floats)
#define KSTRIDE 68             // K/V row stride (floats)
#define SST 132                // score/prob row stride (floats)
#define ATT2_SMEM ((64*QSTRIDE + 128*KSTRIDE + 128*KSTRIDE)*4)   // 87040 B

// ---------------------------------------------------------------------------
// Scratch (device globals: allocation-free rule)
// ---------------------------------------------------------------------------
__device__ float g_Q[(size_t)MM * DD];
__device__ float g_K[(size_t)MM * DD];
__device__ float g_V[(size_t)MM * DD];
__device__ __half g_Ah[(size_t)MM * DD];
__device__ __half g_Au[(size_t)MM * DD];
__device__ __half g_Wh[(size_t)4 * DD * DD];   // wq,wk,wv,wo
__device__ __half g_Wu[(size_t)4 * DD * DD];
__device__ __half g_Ch[(size_t)MM * DD];
__device__ __half g_Cu[(size_t)MM * DD];

// ---------------------------------------------------------------------------
// Helpers
// ---------------------------------------------------------------------------
__device__ __forceinline__ uint32_t smem_u32(const void* p) {
    uint32_t a;
    asm("{ .reg .u64 t; cvta.to.shared.u64 t, %1; cvt.u32.u64 %0, t; }"
        : "=r"(a) : "l"(p));
    return a;
}

__device__ __forceinline__ void cpasync16(uint32_t dst, const void* src) {
    asm volatile("cp.async.cg.shared.global [%0], [%1], 16;"
                 :: "r"(dst), "l"(src));
}
#define CP_COMMIT() asm volatile("cp.async.commit_group;" ::: "memory")
#define CP_WAIT1()  asm volatile("cp.async.wait_group 1;" ::: "memory")
#define CP_WAIT0()  asm volatile("cp.async.wait_group 0;" ::: "memory")

__device__ __forceinline__ void ldm4(uint32_t* r, uint32_t addr) {
    asm volatile("ldmatrix.sync.aligned.m8n8.x4.shared.b16 {%0,%1,%2,%3}, [%4];"
                 : "=r"(r[0]), "=r"(r[1]), "=r"(r[2]), "=r"(r[3]) : "r"(addr));
}

__device__ __forceinline__ void mma_f32(float* c, const uint32_t* a,
                                        uint32_t b0, uint32_t b1) {
    asm volatile(
        "mma.sync.aligned.m16n8k16.row.col.f32.f16.f16.f32 "
        "{%0,%1,%2,%3}, {%4,%5,%6,%7}, {%8,%9}, {%0,%1,%2,%3};"
        : "+f"(c[0]), "+f"(c[1]), "+f"(c[2]), "+f"(c[3])
        : "r"(a[0]), "r"(a[1]), "r"(a[2]), "r"(a[3]), "r"(b0), "r"(b1));
}

// x -> H = fp16(x), U = fp16(2^-3*H + 2^3*(x-H))
__device__ __forceinline__ void ksplit(float x, __half& h, __half& u) {
    h = __float2half_rn(x);
    const float hf = __half2float(h);
    u = __float2half_rn(fmaf(0.125f, hf, 8.0f * (x - hf)));
}

// ---------------------------------------------------------------------------
// Split pass: q + 4 weights -> fp16 H / U
// ---------------------------------------------------------------------------
__global__ void __launch_bounds__(256) split_kernel(const float* __restrict__ q,
                                                    const float* __restrict__ wq,
                                                    const float* __restrict__ wk,
                                                    const float* __restrict__ wv,
                                                    const float* __restrict__ wo)
{
    const size_t i4 = (size_t)blockIdx.x * 256 + threadIdx.x;
    const float* src;
    __half *dh, *du;
    size_t e;
    if (i4 < 1048576) {
        src = q; e = i4;
        dh = g_Ah; du = g_Au;
    } else {
        const size_t r = i4 - 1048576;
        const int w = (int)(r >> 18);
        e = r & 262143;
        src = (w == 0) ? wq : (w == 1) ? wk : (w == 2) ? wv : wo;
        dh = g_Wh + (size_t)w * DD * DD;
        du = g_Wu + (size_t)w * DD * DD;
    }
    const float4 v = ((const float4*)src)[e];
    __half h[4], u[4];
    ksplit(v.x, h[0], u[0]); ksplit(v.y, h[1], u[1]);
    ksplit(v.z, h[2], u[2]); ksplit(v.w, h[3], u[3]);
    *(ushort4*)(dh + e * 4) = make_ushort4(*(unsigned short*)&h[0], *(unsigned short*)&h[1],
                                           *(unsigned short*)&h[2], *(unsigned short*)&h[3]);
    *(ushort4*)(du + e * 4) = make_ushort4(*(unsigned short*)&u[0], *(unsigned short*)&u[1],
                                           *(unsigned short*)&u[2], *(unsigned short*)&u[3]);
}

// ---------------------------------------------------------------------------
// fp16 Karatsuba GEMM (unchanged from round 9)
// ---------------------------------------------------------------------------
__device__ __forceinline__ void gemm_body(const __half* __restrict__ Ah,
                                          const __half* __restrict__ Au,
                                          const __half* __restrict__ Wh,
                                          const __half* __restrict__ Wu,
                                          float* __restrict__ C,
                                          const float* __restrict__ bias)
{
    extern __shared__ char dsm[];
    const uint32_t sb = smem_u32(dsm);
    const int tid  = threadIdx.x;
    const int wid  = tid >> 5;
    const int lane = tid & 31;
    const int wm   = wid >> 2;
    const int wn   = wid & 3;
    const int brow = blockIdx.y * TM;
    const int bcol = blockIdx.x * TN;

    const __half* Abase[2] = { Ah + (size_t)brow * DD, Au + (size_t)brow * DD };
    const __half* Bbase[2] = { Wh + (size_t)bcol * DD, Wu + (size_t)bcol * DD };

    float acc[4][4][4];
    float acc2[4][4][4];
#pragma unroll
    for (int a = 0; a < 4; ++a)
#pragma unroll
        for (int b = 0; b < 4; ++b)
#pragma unroll
            for (int c = 0; c < 4; ++c) { acc[a][b][c] = 0.f; acc2[a][b][c] = 0.f; }

    auto issue = [&](int kc, int stg) {
#pragma unroll
        for (int arr = 0; arr < 4; ++arr) {
            const __half* g = (arr < 2) ? Abase[arr] : Bbase[arr - 2];
            const uint32_t sdst = sb + stg * STAGE_BYTES + arr * ARR_BYTES;
#pragma unroll
            for (int it = 0; it < 4; ++it) {
                const int id = tid + it * 256;
                const int r = id >> 3, c = id & 7;
                const void* src = g + (size_t)r * DD + kc * KC + c * 8;
                const uint32_t dst = sdst + r * 128 + ((c ^ (r & 7)) << 4);
                cpasync16(dst, src);
            }
        }
        CP_COMMIT();
    };

    issue(0, 0);
    issue(1, 1);

    for (int kc = 0; kc < NCH; ++kc) {
        if (kc + 1 < NCH) CP_WAIT1(); else CP_WAIT0();
        __syncthreads();
        if (kc + 2 < NCH) issue(kc + 2, (kc + 2) % NSTAGE);

        const uint32_t st = sb + (kc % NSTAGE) * STAGE_BYTES;
#pragma unroll
        for (int kk = 0; kk < 4; ++kk) {
            const int c16 = kk * 2 + (lane >> 4);
            uint32_t aoff[4], boff[2];
#pragma unroll
            for (int mi = 0; mi < 4; ++mi) {
                const int row = wm * 64 + mi * 16 + (lane & 15);
                aoff[mi] = row * 128 + ((c16 ^ (row & 7)) << 4);
            }
#pragma unroll
            for (int nb = 0; nb < 2; ++nb) {
                const int row = wn * 32 + nb * 16 + (lane & 15);
                boff[nb] = row * 128 + ((c16 ^ (row & 7)) << 4);
            }
            uint32_t ah[4][4], bh[2][4], au[4][4], bu[2][4];
#pragma unroll
            for (int mi = 0; mi < 4; ++mi) ldm4(ah[mi], st + OFF_AH + aoff[mi]);
#pragma unroll
            for (int nb = 0; nb < 2; ++nb) ldm4(bh[nb], st + OFF_BH + boff[nb]);
#pragma unroll
            for (int mi = 0; mi < 4; ++mi) ldm4(au[mi], st + OFF_AU + aoff[mi]);
#pragma unroll
            for (int nb = 0; nb < 2; ++nb) ldm4(bu[nb], st + OFF_BU + boff[nb]);
#pragma unroll
            for (int mi = 0; mi < 4; ++mi)
#pragma unroll
                for (int ni = 0; ni < 4; ++ni) {
                    const int nb = ni >> 1, sidx = ni & 1;
                    mma_f32(acc[mi][ni], ah[mi], bh[nb][sidx], bh[nb][sidx + 2]);
                }
#pragma unroll
            for (int mi = 0; mi < 4; ++mi)
#pragma unroll
                for (int ni = 0; ni < 4; ++ni) {
                    const int nb = ni >> 1, sidx = ni & 1;
                    mma_f32(acc2[mi][ni], au[mi], bu[nb][sidx], bu[nb][sidx + 2]);
                }
        }
    }

#pragma unroll
    for (int mi = 0; mi < 4; ++mi) {
        const int row = brow + wm * 64 + mi * 16 + (lane >> 2);
#pragma unroll
        for (int ni = 0; ni < 4; ++ni) {
            const int col = bcol + wn * 32 + ni * 8 + (lane & 3) * 2;
            float2 v0 = make_float2(fmaf(C_MAIN, acc[mi][ni][0], acc2[mi][ni][0]),
                                    fmaf(C_MAIN, acc[mi][ni][1], acc2[mi][ni][1]));
            float2 v1 = make_float2(fmaf(C_MAIN, acc[mi][ni][2], acc2[mi][ni][2]),
                                    fmaf(C_MAIN, acc[mi][ni][3], acc2[mi][ni][3]));
            if (bias) {
                const float b0 = bias[col], b1 = bias[col + 1];
                v0.x += b0; v0.y += b1; v1.x += b0; v1.y += b1;
            }
            *(float2*)&C[(size_t)row * DD + col]       = v0;
            *(float2*)&C[(size_t)(row + 8) * DD + col] = v1;
        }
    }
}

__global__ void __launch_bounds__(256, 1) qkv_bf()
{
    const int z = blockIdx.z;
    float* Cc = (z == 0) ? g_Q : ((z == 1) ? g_K : g_V);
    gemm_body(g_Ah, g_Au,
              g_Wh + (size_t)z * DD * DD, g_Wu + (size_t)z * DD * DD,
              Cc, nullptr);
}

__global__ void __launch_bounds__(256, 1) out_bf(const float* __restrict__ bo,
                                                 float* __restrict__ out)
{
    gemm_body(g_Ch, g_Cu,
              g_Wh + (size_t)3 * DD * DD, g_Wu + (size_t)3 * DD * DD,
              out, bo);
}

// ---------------------------------------------------------------------------
// Attention v2: register-tiled. Block = 64 queries x (b,h), 128-key window.
//   Phase 1 (scores): warp w owns key cols [16w,16w+16); thread tile 8q x 4k.
//   Phase 2 (softmax): 4 threads/row over the S tile in SMEM (aliases K).
//   Phase 3 (PV): warp w owns q rows [8w,8w+8); thread tile 1q x 16d.
// ---------------------------------------------------------------------------
__global__ void __launch_bounds__(256) attn_v2(float* __restrict__ attn_out)
{
    extern __shared__ float s[];
    float* Qs = s;                          // 64 x QSTRIDE
    float* Ks = s + 64 * QSTRIDE;           // 128 x KSTRIDE
    float* Vs = Ks + 128 * KSTRIDE;         // 128 x KSTRIDE
    float* Ss = Ks;                         // 64 x SST (aliases Ks; used after)

    const int tid  = threadIdx.x;
    const int warp = tid >> 5;
    const int lane = tid & 31;
    const int q0   = blockIdx.x * 64;
    const int bh   = blockIdx.y;
    const int h    = bh & (HH - 1);
    const int b    = bh >> 4;
    const int jbase = q0 - 32;

    const float* Qg = g_Q + ((size_t)(b * SS + q0)) * DD + h * 64;
    const float* Kg = g_K + (size_t)b * SS * DD + h * 64;
    const float* Vg = g_V + (size_t)b * SS * DD + h * 64;

    for (int idx = tid; idx < 64 * 16; idx += 256) {
        const int r = idx >> 4, c = idx & 15;
        *(float4*)&Qs[r * QSTRIDE + c * 4] = *(const float4*)&Qg[(size_t)r * DD + c * 4];
    }
    for (int idx = tid; idx < 128 * 16; idx += 256) {
        const int r = idx >> 4, c = idx & 15;
        const int j = jbase + r;
        if (j >= 0 && j < SS) {
            *(float4*)&Ks[r * KSTRIDE + c * 4] = *(const float4*)&Kg[(size_t)j * DD + c * 4];
            *(float4*)&Vs[r * KSTRIDE + c * 4] = *(const float4*)&Vg[(size_t)j * DD + c * 4];
        } else {
            *(float4*)&Vs[r * KSTRIDE + c * 4] = make_float4(0.f, 0.f, 0.f, 0.f);
        }
    }
    __syncthreads();

    // ---- scores ----
    const int tq = lane >> 2;       // 0..7
    const int tk = lane & 3;        // 0..3
    float sacc[8][4];
#pragma unroll
    for (int i = 0; i < 8; ++i)
#pragma unroll
        for (int j = 0; j < 4; ++j) sacc[i][j] = 0.f;

    {
        const float* Qp = Qs + tq * QSTRIDE;
        const float* Kp = Ks + (16 * warp + tk) * KSTRIDE;
#pragma unroll 4
        for (int d = 0; d < 64; ++d) {
            float qv[8], kv[4];
#pragma unroll
            for (int i = 0; i < 8; ++i) qv[i] = Qp[i * 8 * QSTRIDE + d];
#pragma unroll
            for (int j = 0; j < 4; ++j) kv[j] = Kp[j * 4 * KSTRIDE + d];
#pragma unroll
            for (int i = 0; i < 8; ++i)
#pragma unroll
                for (int j = 0; j < 4; ++j)
                    sacc[i][j] = fmaf(qv[i], kv[j], sacc[i][j]);
        }
    }
    __syncthreads();   // all Ks reads done before Ss (alias) is written

#pragma unroll
    for (int i = 0; i < 8; ++i) {
        const int qrow = tq + 8 * i;
#pragma unroll
        for (int j = 0; j < 4; ++j) {
            const int kcol = 16 * warp + tk + 4 * j;
            const int jg = jbase + kcol;
            const bool val = (jg >= 0) && (jg < SS) &&
                             (kcol >= qrow) && (kcol <= qrow + 64);
            Ss[qrow * SST + kcol] = val ? sacc[i][j] * 0.125f : -1e30f;
        }
    }
    __syncthreads();

    // ---- softmax (4 threads per row) ----
    {
        const int r = tid >> 2, p = tid & 3;
        const int ig = q0 + r;
        const int jlo = max(0, ig - 32), jhi = min(SS - 1, ig + 32);
        const int rb = jlo - jbase, n = jhi - jlo + 1;
        float* Sr = Ss + r * SST;

        float m = -1e30f;
#pragma unroll
        for (int c4 = 0; c4 < 32; ++c4) m = fmaxf(m, Sr[p + 4 * c4]);
        m = fmaxf(m, __shfl_xor_sync(0xffffffffu, m, 1));
        m = fmaxf(m, __shfl_xor_sync(0xffffffffu, m, 2));

        float sum = 0.f;
#pragma unroll
        for (int c4 = 0; c4 < 32; ++c4) {
            const int c = p + 4 * c4;
            float e = 0.f;
            if (c >= rb && c < rb + n) e = __expf(Sr[c] - m);
            Sr[c] = e;
            sum += e;
        }
        sum += __shfl_xor_sync(0xffffffffu, sum, 1);
        sum += __shfl_xor_sync(0xffffffffu, sum, 2);
        const float inv = 1.f / sum;

        float* rowp = attn_out ? (attn_out + ((size_t)bh * SS + ig) * SS) : nullptr;
#pragma unroll
        for (int c4 = 0; c4 < 32; ++c4) {
            const int c = p + 4 * c4;
            const float pv = Sr[c] * inv;
            Sr[c] = pv;
            if (rowp && c >= rb && c < rb + n) rowp[jbase + c] = pv;
        }
    }
    __syncthreads();

    // ---- P @ V ----
    {
        const int q  = 8 * warp + (lane >> 2);
        const int dg = lane & 3;
        const float* Pr = Ss + q * SST;
        float cacc[16];
#pragma unroll
        for (int i = 0; i < 16; ++i) cacc[i] = 0.f;

        for (int k = 0; k < 128; ++k) {
            const float pk = Pr[k];
            const float* Vr = Vs + k * KSTRIDE + 4 * dg;
#pragma unroll
            for (int c = 0; c < 4; ++c) {
                const float4 v = *(const float4*)&Vr[16 * c];
                cacc[c * 4 + 0] = fmaf(pk, v.x, cacc[c * 4 + 0]);
                cacc[c * 4 + 1] = fmaf(pk, v.y, cacc[c * 4 + 1]);
                cacc[c * 4 + 2] = fmaf(pk, v.z, cacc[c * 4 + 2]);
                cacc[c * 4 + 3] = fmaf(pk, v.w, cacc[c * 4 + 3]);
            }
        }

        const size_t co = ((size_t)(b * SS + q0 + q)) * DD + h * 64;
#pragma unroll
        for (int c = 0; c < 4; ++c) {
            __half hh[4], uu[4];
#pragma unroll
            for (int e = 0; e < 4; ++e) ksplit(cacc[c * 4 + e], hh[e], uu[e]);
            const int d = 4 * dg + 16 * c;
            *(ushort4*)(g_Ch + co + d) =
                make_ushort4(*(unsigned short*)&hh[0], *(unsigned short*)&hh[1],
                             *(unsigned short*)&hh[2], *(unsigned short*)&hh[3]);
            *(ushort4*)(g_Cu + co + d) =
                make_ushort4(*(unsigned short*)&uu[0], *(unsigned short*)&uu[1],
                             *(unsigned short*)&uu[2], *(unsigned short*)&uu[3]);
        }
    }
}

// ---------------------------------------------------------------------------
extern "C" void kernel_launch(void* const* d_in, const int* in_sizes, int n_in,
                              void* d_out, int out_size)
{
    const float* q  = (const float*)d_in[0];
    const float* wq = (const float*)d_in[1];
    const float* wk = (const float*)d_in[2];
    const float* wv = (const float*)d_in[3];
    const float* wo = (const float*)d_in[4];
    const float* bo = (const float*)d_in[5];
    float* out = (float*)d_out;

    const size_t out_elems  = (size_t)BB * SS * DD;
    const bool   write_attn = (size_t)out_size > out_elems;
    float* attn = out + out_elems;

    static cudaStream_t s2 = nullptr;
    static cudaEvent_t evF = nullptr, evJ = nullptr;
    if (!s2) {
        cudaStreamCreateWithFlags(&s2, cudaStreamNonBlocking);
        cudaEventCreateWithFlags(&evF, cudaEventDisableTiming);
        cudaEventCreateWithFlags(&evJ, cudaEventDisableTiming);
        cudaFuncSetAttribute(qkv_bf,  cudaFuncAttributeMaxDynamicSharedMemorySize, GEMM_SMEM);
        cudaFuncSetAttribute(out_bf,  cudaFuncAttributeMaxDynamicSharedMemorySize, GEMM_SMEM);
        cudaFuncSetAttribute(attn_v2, cudaFuncAttributeMaxDynamicSharedMemorySize, ATT2_SMEM);
    }

    if (write_attn) {
        cudaEventRecord(evF, 0);
        cudaStreamWaitEvent(s2, evF, 0);
        cudaMemsetAsync(attn, 0, (size_t)BB * HH * SS * SS * sizeof(float), s2);
        cudaEventRecord(evJ, s2);
    }

    // 1) split q + weights into fp16 H / U
    split_kernel<<<8192, 256>>>(q, wq, wk, wv, wo);

    // 2) QKV projections (Karatsuba 2-MMA)
    dim3 gq3(DD / TN, MM / TM, 3);
    qkv_bf<<<gq3, 256, GEMM_SMEM>>>();

    if (write_attn) cudaStreamWaitEvent(0, evJ, 0);

    // 3) register-tiled local attention, writes split context + band
    dim3 ga(SS / 64, BB * HH);
    attn_v2<<<ga, 256, ATT2_SMEM>>>(write_attn ? attn : nullptr);

    // 4) output projection + bias (Karatsuba 2-MMA)
    dim3 go(DD / TN, MM / TM, 1);
    out_bf<<<go, 256, GEMM_SMEM>>>(bo, out);
}